// round 15
// baseline (speedup 1.0000x reference)
#include <cuda_runtime.h>
#include <cstdint>

// Problem constants
#define Bn  16
#define Cn  32
#define Nn  128
#define Tn  12
#define COn 64
#define NT  (Nn * Tn)          // 1536 floats per (b,i,j) row of A
#define NT4 (NT / 4)           // 384 float4
#define NSLICE (Bn * Cn)       // 512 (b,i) slices

// Spatial split: 80 producer CTAs (pass 1, HBM stream) + 48 consumer CTAs
// (pass 2, L2 re-read). Each CTA: 768 threads = 4 j-groups x 192 (R3 loop).
#define NPROD   80
#define NCONS   48
#define PROP_CTAS (NPROD + NCONS)   // 128
#define THREADS 768
#define NGRP 4
#define GSZ  192
#define JPG  (Nn / NGRP)       // 32
#define WINDOW 96              // produced-ahead credit (slices); ~75MB L2 window
#define PROP_PAD (90 * 1024)   // 36KB static + 90KB -> guaranteed 1 CTA/SM

// Scratch: h = concat([x1, x2], channel axis) -> [B][2C][N*T] = 6.3 MB
__device__ float g_h[(size_t)Bn * 2 * Cn * NT];
// per-slice ready flags + consumed counter; memset to 0 each replay
__device__ unsigned int g_flag[NSLICE];
__device__ unsigned int g_consumed;

extern __shared__ char s_pad[];   // occupancy limiter (never accessed)

__device__ __forceinline__ void fma4(float4& acc, const float4 a, const float4 v) {
    acc.x = fmaf(a.x, v.x, acc.x);
    acc.y = fmaf(a.y, v.y, acc.y);
    acc.z = fmaf(a.z, v.z, acc.z);
    acc.w = fmaf(a.w, v.w, acc.w);
}
__device__ __forceinline__ float4 add4(const float4 a, const float4 b) {
    return make_float4(a.x + b.x, a.y + b.y, a.z + b.z, a.w + b.w);
}
__device__ __forceinline__ unsigned int ld_vol_u32(const unsigned int* p) {
    unsigned int v;
    asm volatile("ld.volatile.global.u32 %0, [%1];" : "=r"(v) : "l"(p));
    return v;
}

// ---------------------------------------------------------------------------
// Kernel 1: fused propagation, producer/consumer SM specialization.
// Producers (CTAs 0..79): for slice s = bid, bid+80, ...: stream A[s] from
//   HBM (R3 pass-1 loop, fills L2), reduce, write x1 -> g_h, set g_flag[s].
//   Credit check keeps produced-unconsumed window <= 96 slices in L2.
// Consumers (CTAs 80..127): for slice s = bid-80, +48, ...: spin on flag,
//   load x1 from g_h (L2), run pass 2 reading A[s] from L2 (pure L2-latency
//   stream on these SMs -> no L1tex latency-class mixing), write x2 row,
//   bump g_consumed.
// HBM fills and L2 re-reads proceed CONCURRENTLY on disjoint SMs.
// ---------------------------------------------------------------------------
__global__ __launch_bounds__(THREADS, 1)
void prop_kernel(const float* __restrict__ x, const float* __restrict__ A) {
    __shared__ float4 part[NGRP][NT4];   // 24 KB partial sums
    __shared__ float4 xv_s[NT4];         // x (producer) / x1 (consumer), [j*3+lq]

    const int t  = threadIdx.x;
    const int g  = t / GSZ;
    const int ti = t - g * GSZ;          // 0..191
    const int lq = ti % 3;
    const int j0 = g * JPG;

    if (blockIdx.x < NPROD) {
        // ======================= Producer =======================
        for (int s = blockIdx.x; s < NSLICE; s += NPROD) {
            if (t == 0 && s >= WINDOW) {
                const unsigned int tgt = (unsigned int)(s - WINDOW);
                while (ld_vol_u32(&g_consumed) < tgt) { }
            }
            if (t < NT4) xv_s[t] = ((const float4*)x)[(size_t)s * NT4 + t];
            __syncthreads();   // xs ready; also gates on t0's credit check

            // ---- Pass 1: HBM stream (R3 loop)
            float4 acc0 = make_float4(0.f, 0.f, 0.f, 0.f);
            float4 acc1 = make_float4(0.f, 0.f, 0.f, 0.f);
            {
                const float4* __restrict__ ap =
                    (const float4*)A + ((size_t)s * Nn + j0) * NT4;
#pragma unroll 8
                for (int jj = 0; jj < JPG; ++jj) {
                    float4 a0 = ap[jj * NT4 + ti];
                    float4 a1 = ap[jj * NT4 + ti + GSZ];
                    float4 xv = xv_s[(j0 + jj) * 3 + lq];
                    fma4(acc0, a0, xv);
                    fma4(acc1, a1, xv);
                }
            }
            part[g][ti]       = acc0;
            part[g][ti + GSZ] = acc1;
            __syncthreads();

            // ---- Reduce + write x1 row (g_h x1 row IS h's order-1 half)
            if (t < NT4) {
                float4 r1 = add4(add4(part[0][t], part[1][t]),
                                 add4(part[2][t], part[3][t]));
                const int b = s / Cn;
                const int i = s % Cn;
                ((float4*)(g_h + ((size_t)b * 2 * Cn + i) * NT))[t] = r1;
            }
            __syncthreads();   // all writers done before flag
            if (t == 0) {
                __threadfence();               // release x1 + streamed state
                atomicExch(&g_flag[s], 1u);
            }
        }
    } else {
        // ======================= Consumer =======================
        for (int s = blockIdx.x - NPROD; s < NSLICE; s += NCONS) {
            if (t == 0) {
                while (ld_vol_u32(&g_flag[s]) == 0) { }
                __threadfence();               // acquire x1 writes
            }
            __syncthreads();

            const int b = s / Cn;
            const int i = s % Cn;
            const float4* hrow1 = (const float4*)(g_h + ((size_t)b * 2 * Cn + i) * NT);
            if (t < NT4) xv_s[t] = hrow1[t];
            __syncthreads();

            // ---- Pass 2: pure L2 re-read of A[s] (last-use)
            float4 acc0 = make_float4(0.f, 0.f, 0.f, 0.f);
            float4 acc1 = make_float4(0.f, 0.f, 0.f, 0.f);
            {
                const float4* __restrict__ ap =
                    (const float4*)A + ((size_t)s * Nn + j0) * NT4;
#pragma unroll 8
                for (int jj = 0; jj < JPG; ++jj) {
                    float4 a0 = __ldlu(&ap[jj * NT4 + ti]);
                    float4 a1 = __ldlu(&ap[jj * NT4 + ti + GSZ]);
                    float4 xv = xv_s[(j0 + jj) * 3 + lq];
                    fma4(acc0, a0, xv);
                    fma4(acc1, a1, xv);
                }
            }
            part[g][ti]       = acc0;
            part[g][ti + GSZ] = acc1;
            __syncthreads();

            // ---- Reduce + write x2 row
            if (t < NT4) {
                float4 r2 = add4(add4(part[0][t], part[1][t]),
                                 add4(part[2][t], part[3][t]));
                ((float4*)(g_h + ((size_t)b * 2 * Cn + Cn + i) * NT))[t] = r2;
            }
            __syncthreads();
            if (t == 0) atomicAdd(&g_consumed, 1u);   // release credit
        }
    }
}

// ---------------------------------------------------------------------------
// Kernel 2: 1x1 conv channel mix, smem-tiled GEMM (exact champion version).
// ---------------------------------------------------------------------------
#define MIX_COLS 64
#define MIX_NCB  (NT / MIX_COLS)   // 24

__global__ __launch_bounds__(256) void mix_kernel(const float* __restrict__ W,
                                                  const float* __restrict__ bias,
                                                  float* __restrict__ out) {
    __shared__ float4 hs[(2 * Cn) * (MIX_COLS / 4)];   // 16 KB
    __shared__ float  Ws[COn * 2 * Cn];                // 16 KB
    __shared__ float  bs[COn];

    const int t    = threadIdx.x;
    const int b    = blockIdx.x / MIX_NCB;
    const int col0 = (blockIdx.x % MIX_NCB) * MIX_COLS;
    const int colq = t & 15;
    const int oq   = t >> 4;

    {
        float4*       Wd = (float4*)Ws;
        const float4* W4 = (const float4*)W;
#pragma unroll
        for (int s = 0; s < 4; ++s) Wd[t + 256 * s] = W4[t + 256 * s];
        if (t < COn) bs[t] = bias[t];
    }
    {
        const float* hb = g_h + (size_t)b * 2 * Cn * NT + col0;
#pragma unroll
        for (int s = 0; s < 4; ++s) {
            int idx = t + 256 * s;
            int c   = idx >> 4;
            int v   = idx & 15;
            hs[idx] = ((const float4*)(hb + (size_t)c * NT))[v];
        }
    }
    __syncthreads();

    float4 acc0 = make_float4(bs[4 * oq + 0], bs[4 * oq + 0], bs[4 * oq + 0], bs[4 * oq + 0]);
    float4 acc1 = make_float4(bs[4 * oq + 1], bs[4 * oq + 1], bs[4 * oq + 1], bs[4 * oq + 1]);
    float4 acc2 = make_float4(bs[4 * oq + 2], bs[4 * oq + 2], bs[4 * oq + 2], bs[4 * oq + 2]);
    float4 acc3 = make_float4(bs[4 * oq + 3], bs[4 * oq + 3], bs[4 * oq + 3], bs[4 * oq + 3]);

#pragma unroll 8
    for (int c = 0; c < 2 * Cn; ++c) {
        float4 hv = hs[c * 16 + colq];
        float  w0 = Ws[(4 * oq + 0) * 2 * Cn + c];
        float  w1 = Ws[(4 * oq + 1) * 2 * Cn + c];
        float  w2 = Ws[(4 * oq + 2) * 2 * Cn + c];
        float  w3 = Ws[(4 * oq + 3) * 2 * Cn + c];
        acc0.x = fmaf(w0, hv.x, acc0.x); acc0.y = fmaf(w0, hv.y, acc0.y);
        acc0.z = fmaf(w0, hv.z, acc0.z); acc0.w = fmaf(w0, hv.w, acc0.w);
        acc1.x = fmaf(w1, hv.x, acc1.x); acc1.y = fmaf(w1, hv.y, acc1.y);
        acc1.z = fmaf(w1, hv.z, acc1.z); acc1.w = fmaf(w1, hv.w, acc1.w);
        acc2.x = fmaf(w2, hv.x, acc2.x); acc2.y = fmaf(w2, hv.y, acc2.y);
        acc2.z = fmaf(w2, hv.z, acc2.z); acc2.w = fmaf(w2, hv.w, acc2.w);
        acc3.x = fmaf(w3, hv.x, acc3.x); acc3.y = fmaf(w3, hv.y, acc3.y);
        acc3.z = fmaf(w3, hv.z, acc3.z); acc3.w = fmaf(w3, hv.w, acc3.w);
    }

    float* ob = out + (size_t)b * COn * NT + col0;
    ((float4*)(ob + (size_t)(4 * oq + 0) * NT))[colq] = acc0;
    ((float4*)(ob + (size_t)(4 * oq + 1) * NT))[colq] = acc1;
    ((float4*)(ob + (size_t)(4 * oq + 2) * NT))[colq] = acc2;
    ((float4*)(ob + (size_t)(4 * oq + 3) * NT))[colq] = acc3;
}

// ---------------------------------------------------------------------------
extern "C" void kernel_launch(void* const* d_in, const int* in_sizes, int n_in,
                              void* d_out, int out_size) {
    const float* x    = (const float*)d_in[0];   // [B,C,N,T]
    const float* A    = (const float*)d_in[1];   // [B,C,N,N,T]
    const float* W    = (const float*)d_in[2];   // [C_OUT, 2C]
    const float* bias = (const float*)d_in[3];   // [C_OUT]
    float* out = (float*)d_out;                  // [B,C_OUT,N,T]

    // reset flags + consumed counter each replay (captured memset nodes)
    void* fp = nullptr; void* cp = nullptr;
    cudaGetSymbolAddress(&fp, g_flag);
    cudaGetSymbolAddress(&cp, g_consumed);
    cudaMemsetAsync(fp, 0, sizeof(unsigned int) * NSLICE);
    cudaMemsetAsync(cp, 0, sizeof(unsigned int));

    cudaFuncSetAttribute(prop_kernel, cudaFuncAttributeMaxDynamicSharedMemorySize, PROP_PAD);

    prop_kernel<<<PROP_CTAS, THREADS, PROP_PAD>>>(x, A);
    mix_kernel<<<Bn * MIX_NCB, 256>>>(W, bias, out);
}

// round 16
// speedup vs baseline: 1.2116x; 1.2116x over previous
#include <cuda_runtime.h>

// Problem constants
#define Bn  16
#define Cn  32
#define Nn  128
#define Tn  12
#define COn 64
#define NT  (Nn * Tn)          // 1536 floats per (b,i,j) row of A
#define NT4 (NT / 4)           // 384 float4
#define NSLICE (Bn * Cn)       // 512 (b,i) slices

// prop config (R3 structure, proven 92us): 128 persistent CTAs (1/SM via
// smem pad), 768 threads = 4 groups x 192; group g streams j in [32g,32g+32).
#define PROP_CTAS    128
#define PROP_THREADS 768
#define NGRP 4
#define GSZ  192
#define JPG  (Nn / NGRP)       // 32
#define NITER (NSLICE / PROP_CTAS)   // 4
#define PROP_PAD (150 * 1024)  // dummy dynamic smem -> 1 CTA/SM

// Scratch: h = concat([x1, x2], channel axis) -> [B][2C][N*T] = 6.3 MB
__device__ float g_h[(size_t)Bn * 2 * Cn * NT];

extern __shared__ char s_pad[];   // occupancy limiter (never accessed)

__device__ __forceinline__ void fma4(float4& acc, const float4 a, const float4 v) {
    acc.x = fmaf(a.x, v.x, acc.x);
    acc.y = fmaf(a.y, v.y, acc.y);
    acc.z = fmaf(a.z, v.z, acc.z);
    acc.w = fmaf(a.w, v.w, acc.w);
}
__device__ __forceinline__ float4 add4(const float4 a, const float4 b) {
    return make_float4(a.x + b.x, a.y + b.y, a.z + b.z, a.w + b.w);
}

// ---------------------------------------------------------------------------
// Kernel 1: fused order-1 + order-2 propagation (R3, proven) with two
// latency shaves: h-x1 row stored during reduce-1 (drains under pass 2),
// and next slice's x prefetched into a register shadow during pass 2
// (removes the x-load latency from the loop-top critical path).
// Pass 1 streams each slice from HBM (fills L2); pass 2 re-reads from L2.
// Phase-locked footprint 128 x 786KB = 100MB <= 126MB.
// ---------------------------------------------------------------------------
__global__ __launch_bounds__(PROP_THREADS, 1)
void prop_kernel(const float* __restrict__ x, const float* __restrict__ A) {
    __shared__ float4 part[NGRP][NT4];   // 24 KB partial sums
    __shared__ float4 xs[NT4];           // x slice,  [j*3 + lq]
    __shared__ float4 x1s[NT4];          // x1 slice, same layout

    const int t  = threadIdx.x;
    const int g  = t / GSZ;
    const int ti = t - g * GSZ;          // 0..191
    const int lq = ti % 3;
    const int j0 = g * JPG;
    const float4* __restrict__ x4 = (const float4*)x;

    // Prologue: x for the first slice
    if (t < NT4) xs[t] = x4[(size_t)blockIdx.x * NT4 + t];
    __syncthreads();

    for (int it = 0; it < NITER; ++it) {
        const int bc = blockIdx.x + it * PROP_CTAS;
        const float4* __restrict__ Ap = (const float4*)(A + (size_t)bc * Nn * NT);
        const int b = bc / Cn;
        const int i = bc % Cn;
        float4* hrow1 = (float4*)(g_h + ((size_t)b * 2 * Cn + i) * NT);
        float4* hrow2 = (float4*)(g_h + ((size_t)b * 2 * Cn + Cn + i) * NT);

        // ---- Pass 1: x1[k,l] = sum_j x[j,l] * A[j,k,l]  (HBM stream)
        float4 acc0 = make_float4(0.f, 0.f, 0.f, 0.f);
        float4 acc1 = make_float4(0.f, 0.f, 0.f, 0.f);
        {
            const float4* __restrict__ ap = Ap + (size_t)j0 * NT4;
#pragma unroll 4
            for (int jj = 0; jj < JPG; ++jj) {
                float4 a0 = ap[jj * NT4 + ti];
                float4 a1 = ap[jj * NT4 + ti + GSZ];
                float4 xv = xs[(j0 + jj) * 3 + lq];
                fma4(acc0, a0, xv);
                fma4(acc1, a1, xv);
            }
        }
        part[g][ti]       = acc0;
        part[g][ti + GSZ] = acc1;
        __syncthreads();

        // ---- Reduce 1: x1 = sum of 4 partials; store h x1 row NOW
        if (t < NT4) {
            float4 r1 = add4(add4(part[0][t], part[1][t]),
                             add4(part[2][t], part[3][t]));
            x1s[t]    = r1;
            hrow1[t]  = r1;      // STG drains while pass 2 runs
        }
        __syncthreads();

        // ---- prefetch next slice's x into a register shadow (1 LDG/thread)
        const bool has_next = (it + 1 < NITER);
        float4 xnext;
        if (has_next && t < NT4)
            xnext = x4[(size_t)(bc + PROP_CTAS) * NT4 + t];

        // ---- Pass 2: x2[k,l] = sum_j x1[j,l] * A[j,k,l]  (L2 re-read)
        acc0 = make_float4(0.f, 0.f, 0.f, 0.f);
        acc1 = make_float4(0.f, 0.f, 0.f, 0.f);
        {
            const float4* __restrict__ ap = Ap + (size_t)j0 * NT4;
#pragma unroll 4
            for (int jj = 0; jj < JPG; ++jj) {
                float4 a0 = __ldlu(&ap[jj * NT4 + ti]);
                float4 a1 = __ldlu(&ap[jj * NT4 + ti + GSZ]);
                float4 xv = x1s[(j0 + jj) * 3 + lq];
                fma4(acc0, a0, xv);
                fma4(acc1, a1, xv);
            }
        }
        part[g][ti]       = acc0;
        part[g][ti + GSZ] = acc1;
        // commit x shadow: xs is dead during pass 2 (pass 1 readers long done)
        if (has_next && t < NT4) xs[t] = xnext;
        __syncthreads();

        // ---- Reduce 2 + write h x2 row
        if (t < NT4) {
            float4 r2 = add4(add4(part[0][t], part[1][t]),
                             add4(part[2][t], part[3][t]));
            hrow2[t] = r2;
        }
        __syncthreads();   // protects part[] reads vs next pass-1 writes
    }
}

// ---------------------------------------------------------------------------
// Kernel 2: 1x1 conv channel mix, smem-tiled GEMM (champion tiling) with an
// explicit software pipeline: hv / w for iteration c+1 are loaded while c's
// 16 FFMAs issue, breaking the 29-cycle LDS->FFMA dependency that held
// issue at 49%. Block: 256 threads, tile = 64 outs x 64 cols.
// ---------------------------------------------------------------------------
#define MIX_COLS 64
#define MIX_NCB  (NT / MIX_COLS)   // 24

__global__ __launch_bounds__(256) void mix_kernel(const float* __restrict__ W,
                                                  const float* __restrict__ bias,
                                                  float* __restrict__ out) {
    __shared__ float4 hs[(2 * Cn) * (MIX_COLS / 4)];   // 16 KB
    __shared__ float  Ws[COn * 2 * Cn];                // 16 KB
    __shared__ float  bs[COn];

    const int t    = threadIdx.x;
    const int b    = blockIdx.x / MIX_NCB;
    const int col0 = (blockIdx.x % MIX_NCB) * MIX_COLS;
    const int colq = t & 15;
    const int oq   = t >> 4;

    {
        float4*       Wd = (float4*)Ws;
        const float4* W4 = (const float4*)W;
#pragma unroll
        for (int s = 0; s < 4; ++s) Wd[t + 256 * s] = W4[t + 256 * s];
        if (t < COn) bs[t] = bias[t];
    }
    {
        const float* hb = g_h + (size_t)b * 2 * Cn * NT + col0;
#pragma unroll
        for (int s = 0; s < 4; ++s) {
            int idx = t + 256 * s;
            int c   = idx >> 4;
            int v   = idx & 15;
            hs[idx] = ((const float4*)(hb + (size_t)c * NT))[v];
        }
    }
    __syncthreads();

    float4 acc0 = make_float4(bs[4 * oq + 0], bs[4 * oq + 0], bs[4 * oq + 0], bs[4 * oq + 0]);
    float4 acc1 = make_float4(bs[4 * oq + 1], bs[4 * oq + 1], bs[4 * oq + 1], bs[4 * oq + 1]);
    float4 acc2 = make_float4(bs[4 * oq + 2], bs[4 * oq + 2], bs[4 * oq + 2], bs[4 * oq + 2]);
    float4 acc3 = make_float4(bs[4 * oq + 3], bs[4 * oq + 3], bs[4 * oq + 3], bs[4 * oq + 3]);

    // software-pipelined inner loop
    float4 hv = hs[colq];
    float  w0 = Ws[(4 * oq + 0) * 2 * Cn];
    float  w1 = Ws[(4 * oq + 1) * 2 * Cn];
    float  w2 = Ws[(4 * oq + 2) * 2 * Cn];
    float  w3 = Ws[(4 * oq + 3) * 2 * Cn];
#pragma unroll
    for (int c = 0; c < 2 * Cn; ++c) {
        float4 hvn = hv;
        float  w0n = w0, w1n = w1, w2n = w2, w3n = w3;
        if (c + 1 < 2 * Cn) {
            hvn = hs[(c + 1) * 16 + colq];
            w0n = Ws[(4 * oq + 0) * 2 * Cn + c + 1];
            w1n = Ws[(4 * oq + 1) * 2 * Cn + c + 1];
            w2n = Ws[(4 * oq + 2) * 2 * Cn + c + 1];
            w3n = Ws[(4 * oq + 3) * 2 * Cn + c + 1];
        }
        acc0.x = fmaf(w0, hv.x, acc0.x); acc0.y = fmaf(w0, hv.y, acc0.y);
        acc0.z = fmaf(w0, hv.z, acc0.z); acc0.w = fmaf(w0, hv.w, acc0.w);
        acc1.x = fmaf(w1, hv.x, acc1.x); acc1.y = fmaf(w1, hv.y, acc1.y);
        acc1.z = fmaf(w1, hv.z, acc1.z); acc1.w = fmaf(w1, hv.w, acc1.w);
        acc2.x = fmaf(w2, hv.x, acc2.x); acc2.y = fmaf(w2, hv.y, acc2.y);
        acc2.z = fmaf(w2, hv.z, acc2.z); acc2.w = fmaf(w2, hv.w, acc2.w);
        acc3.x = fmaf(w3, hv.x, acc3.x); acc3.y = fmaf(w3, hv.y, acc3.y);
        acc3.z = fmaf(w3, hv.z, acc3.z); acc3.w = fmaf(w3, hv.w, acc3.w);
        hv = hvn; w0 = w0n; w1 = w1n; w2 = w2n; w3 = w3n;
    }

    float* ob = out + (size_t)b * COn * NT + col0;
    ((float4*)(ob + (size_t)(4 * oq + 0) * NT))[colq] = acc0;
    ((float4*)(ob + (size_t)(4 * oq + 1) * NT))[colq] = acc1;
    ((float4*)(ob + (size_t)(4 * oq + 2) * NT))[colq] = acc2;
    ((float4*)(ob + (size_t)(4 * oq + 3) * NT))[colq] = acc3;
}

// ---------------------------------------------------------------------------
extern "C" void kernel_launch(void* const* d_in, const int* in_sizes, int n_in,
                              void* d_out, int out_size) {
    const float* x    = (const float*)d_in[0];   // [B,C,N,T]
    const float* A    = (const float*)d_in[1];   // [B,C,N,N,T]
    const float* W    = (const float*)d_in[2];   // [C_OUT, 2C]
    const float* bias = (const float*)d_in[3];   // [C_OUT]
    float* out = (float*)d_out;                  // [B,C_OUT,N,T]

    cudaFuncSetAttribute(prop_kernel, cudaFuncAttributeMaxDynamicSharedMemorySize, PROP_PAD);

    prop_kernel<<<PROP_CTAS, PROP_THREADS, PROP_PAD>>>(x, A);
    mix_kernel<<<Bn * MIX_NCB, 256>>>(W, bias, out);
}

// round 17
// speedup vs baseline: 1.2142x; 1.0022x over previous
#include <cuda_runtime.h>

// Problem constants
#define Bn  16
#define Cn  32
#define Nn  128
#define Tn  12
#define COn 64
#define NT  (Nn * Tn)          // 1536 floats per (b,i,j) row of A
#define NT4 (NT / 4)           // 384 float4
#define NSLICE (Bn * Cn)       // 512 (b,i) slices

// prop config (R3 structure, proven 92us): 128 persistent CTAs (1/SM via
// smem pad), 768 threads = 4 groups x 192; group g streams j in [32g,32g+32).
#define PROP_CTAS    128
#define PROP_THREADS 768
#define NGRP 4
#define GSZ  192
#define JPG  (Nn / NGRP)       // 32
#define NITER (NSLICE / PROP_CTAS)   // 4
#define PROP_PAD (150 * 1024)  // dummy dynamic smem -> 1 CTA/SM

// Scratch: h = concat([x1, x2], channel axis) -> [B][2C][N*T] = 6.3 MB
__device__ float g_h[(size_t)Bn * 2 * Cn * NT];

extern __shared__ char s_pad[];   // occupancy limiter (never accessed)

__device__ __forceinline__ void fma4(float4& acc, const float4 a, const float4 v) {
    acc.x = fmaf(a.x, v.x, acc.x);
    acc.y = fmaf(a.y, v.y, acc.y);
    acc.z = fmaf(a.z, v.z, acc.z);
    acc.w = fmaf(a.w, v.w, acc.w);
}
__device__ __forceinline__ float4 add4(const float4 a, const float4 b) {
    return make_float4(a.x + b.x, a.y + b.y, a.z + b.z, a.w + b.w);
}

// ---------------------------------------------------------------------------
// Kernel 1: fused order-1 + order-2 propagation (R16-measured best, 92.1us).
// Pass 1 streams each slice from HBM (fills L2); pass 2 re-reads from L2.
// Phase-locked chip-wide footprint 128 x 786KB = 100MB <= 126MB.
// Shaves vs R3: h-x1 row stored during reduce-1 (STGs drain under pass 2);
// next slice's x prefetched into registers during pass 2.
// ---------------------------------------------------------------------------
__global__ __launch_bounds__(PROP_THREADS, 1)
void prop_kernel(const float* __restrict__ x, const float* __restrict__ A) {
    __shared__ float4 part[NGRP][NT4];   // 24 KB partial sums
    __shared__ float4 xs[NT4];           // x slice,  [j*3 + lq]
    __shared__ float4 x1s[NT4];          // x1 slice, same layout

    const int t  = threadIdx.x;
    const int g  = t / GSZ;
    const int ti = t - g * GSZ;          // 0..191
    const int lq = ti % 3;
    const int j0 = g * JPG;
    const float4* __restrict__ x4 = (const float4*)x;

    // Prologue: x for the first slice
    if (t < NT4) xs[t] = x4[(size_t)blockIdx.x * NT4 + t];
    __syncthreads();

    for (int it = 0; it < NITER; ++it) {
        const int bc = blockIdx.x + it * PROP_CTAS;
        const float4* __restrict__ Ap = (const float4*)(A + (size_t)bc * Nn * NT);
        const int b = bc / Cn;
        const int i = bc % Cn;
        float4* hrow1 = (float4*)(g_h + ((size_t)b * 2 * Cn + i) * NT);
        float4* hrow2 = (float4*)(g_h + ((size_t)b * 2 * Cn + Cn + i) * NT);

        // ---- Pass 1: x1[k,l] = sum_j x[j,l] * A[j,k,l]  (HBM stream)
        float4 acc0 = make_float4(0.f, 0.f, 0.f, 0.f);
        float4 acc1 = make_float4(0.f, 0.f, 0.f, 0.f);
        {
            const float4* __restrict__ ap = Ap + (size_t)j0 * NT4;
#pragma unroll 4
            for (int jj = 0; jj < JPG; ++jj) {
                float4 a0 = ap[jj * NT4 + ti];
                float4 a1 = ap[jj * NT4 + ti + GSZ];
                float4 xv = xs[(j0 + jj) * 3 + lq];
                fma4(acc0, a0, xv);
                fma4(acc1, a1, xv);
            }
        }
        part[g][ti]       = acc0;
        part[g][ti + GSZ] = acc1;
        __syncthreads();

        // ---- Reduce 1: x1 = sum of 4 partials; store h x1 row NOW
        if (t < NT4) {
            float4 r1 = add4(add4(part[0][t], part[1][t]),
                             add4(part[2][t], part[3][t]));
            x1s[t]    = r1;
            hrow1[t]  = r1;      // STG drains while pass 2 runs
        }
        __syncthreads();

        // ---- prefetch next slice's x into a register shadow (1 LDG/thread)
        const bool has_next = (it + 1 < NITER);
        float4 xnext;
        if (has_next && t < NT4)
            xnext = x4[(size_t)(bc + PROP_CTAS) * NT4 + t];

        // ---- Pass 2: x2[k,l] = sum_j x1[j,l] * A[j,k,l]  (L2 re-read)
        acc0 = make_float4(0.f, 0.f, 0.f, 0.f);
        acc1 = make_float4(0.f, 0.f, 0.f, 0.f);
        {
            const float4* __restrict__ ap = Ap + (size_t)j0 * NT4;
#pragma unroll 4
            for (int jj = 0; jj < JPG; ++jj) {
                float4 a0 = __ldlu(&ap[jj * NT4 + ti]);
                float4 a1 = __ldlu(&ap[jj * NT4 + ti + GSZ]);
                float4 xv = x1s[(j0 + jj) * 3 + lq];
                fma4(acc0, a0, xv);
                fma4(acc1, a1, xv);
            }
        }
        part[g][ti]       = acc0;
        part[g][ti + GSZ] = acc1;
        // commit x shadow: xs is dead during pass 2 (pass 1 readers long done)
        if (has_next && t < NT4) xs[t] = xnext;
        __syncthreads();

        // ---- Reduce 2 + write h x2 row
        if (t < NT4) {
            float4 r2 = add4(add4(part[0][t], part[1][t]),
                             add4(part[2][t], part[3][t]));
            hrow2[t] = r2;
        }
        __syncthreads();   // protects part[] reads vs next pass-1 writes
    }
}

// ---------------------------------------------------------------------------
// Kernel 2: 1x1 conv channel mix, smem-tiled GEMM — EXACT R3/champion
// version (measured 10.6us; beat 7 variants). Block: 256 threads,
// tile = 64 outs x 64 cols, thread computes 4 outs x 4 cols.
// ---------------------------------------------------------------------------
#define MIX_COLS 64
#define MIX_NCB  (NT / MIX_COLS)   // 24

__global__ __launch_bounds__(256) void mix_kernel(const float* __restrict__ W,
                                                  const float* __restrict__ bias,
                                                  float* __restrict__ out) {
    __shared__ float4 hs[(2 * Cn) * (MIX_COLS / 4)];   // 16 KB
    __shared__ float  Ws[COn * 2 * Cn];                // 16 KB
    __shared__ float  bs[COn];

    const int t    = threadIdx.x;
    const int b    = blockIdx.x / MIX_NCB;
    const int col0 = (blockIdx.x % MIX_NCB) * MIX_COLS;
    const int colq = t & 15;
    const int oq   = t >> 4;

    {
        float4*       Wd = (float4*)Ws;
        const float4* W4 = (const float4*)W;
#pragma unroll
        for (int s = 0; s < 4; ++s) Wd[t + 256 * s] = W4[t + 256 * s];
        if (t < COn) bs[t] = bias[t];
    }
    {
        const float* hb = g_h + (size_t)b * 2 * Cn * NT + col0;
#pragma unroll
        for (int s = 0; s < 4; ++s) {
            int idx = t + 256 * s;
            int c   = idx >> 4;
            int v   = idx & 15;
            hs[idx] = ((const float4*)(hb + (size_t)c * NT))[v];
        }
    }
    __syncthreads();

    float4 acc0 = make_float4(bs[4 * oq + 0], bs[4 * oq + 0], bs[4 * oq + 0], bs[4 * oq + 0]);
    float4 acc1 = make_float4(bs[4 * oq + 1], bs[4 * oq + 1], bs[4 * oq + 1], bs[4 * oq + 1]);
    float4 acc2 = make_float4(bs[4 * oq + 2], bs[4 * oq + 2], bs[4 * oq + 2], bs[4 * oq + 2]);
    float4 acc3 = make_float4(bs[4 * oq + 3], bs[4 * oq + 3], bs[4 * oq + 3], bs[4 * oq + 3]);

#pragma unroll 8
    for (int c = 0; c < 2 * Cn; ++c) {
        float4 hv = hs[c * 16 + colq];
        float  w0 = Ws[(4 * oq + 0) * 2 * Cn + c];
        float  w1 = Ws[(4 * oq + 1) * 2 * Cn + c];
        float  w2 = Ws[(4 * oq + 2) * 2 * Cn + c];
        float  w3 = Ws[(4 * oq + 3) * 2 * Cn + c];
        acc0.x = fmaf(w0, hv.x, acc0.x); acc0.y = fmaf(w0, hv.y, acc0.y);
        acc0.z = fmaf(w0, hv.z, acc0.z); acc0.w = fmaf(w0, hv.w, acc0.w);
        acc1.x = fmaf(w1, hv.x, acc1.x); acc1.y = fmaf(w1, hv.y, acc1.y);
        acc1.z = fmaf(w1, hv.z, acc1.z); acc1.w = fmaf(w1, hv.w, acc1.w);
        acc2.x = fmaf(w2, hv.x, acc2.x); acc2.y = fmaf(w2, hv.y, acc2.y);
        acc2.z = fmaf(w2, hv.z, acc2.z); acc2.w = fmaf(w2, hv.w, acc2.w);
        acc3.x = fmaf(w3, hv.x, acc3.x); acc3.y = fmaf(w3, hv.y, acc3.y);
        acc3.z = fmaf(w3, hv.z, acc3.z); acc3.w = fmaf(w3, hv.w, acc3.w);
    }

    float* ob = out + (size_t)b * COn * NT + col0;
    ((float4*)(ob + (size_t)(4 * oq + 0) * NT))[colq] = acc0;
    ((float4*)(ob + (size_t)(4 * oq + 1) * NT))[colq] = acc1;
    ((float4*)(ob + (size_t)(4 * oq + 2) * NT))[colq] = acc2;
    ((float4*)(ob + (size_t)(4 * oq + 3) * NT))[colq] = acc3;
}

// ---------------------------------------------------------------------------
extern "C" void kernel_launch(void* const* d_in, const int* in_sizes, int n_in,
                              void* d_out, int out_size) {
    const float* x    = (const float*)d_in[0];   // [B,C,N,T]
    const float* A    = (const float*)d_in[1];   // [B,C,N,N,T]
    const float* W    = (const float*)d_in[2];   // [C_OUT, 2C]
    const float* bias = (const float*)d_in[3];   // [C_OUT]
    float* out = (float*)d_out;                  // [B,C_OUT,N,T]

    cudaFuncSetAttribute(prop_kernel, cudaFuncAttributeMaxDynamicSharedMemorySize, PROP_PAD);

    prop_kernel<<<PROP_CTAS, PROP_THREADS, PROP_PAD>>>(x, A);
    mix_kernel<<<Bn * MIX_NCB, 256>>>(W, bias, out);
}